// round 6
// baseline (speedup 1.0000x reference)
#include <cuda_runtime.h>
#include <cstdint>
#include <math.h>

// AntisymmetricRNN: x_{t+1} = x_t + 0.01*tanh(A x_t + by)
// A = triu(W,1) - triu(W,1)^T - eps*I.  N=256, BS=256, TMAX=1000.
// Persistent kernel: 128 CTAs x 2 batch columns; sequential over time.
// R5: warp-local butterfly reduction (kc within warp), single barrier/step,
//     double-buffered x, own-state + bias in registers.

constexpr int   Nn      = 256;
constexpr int   Tmax    = 1000;
constexpr float STEPF   = 0.01f;
constexpr float EPSF    = 0.001f;
constexpr int   THREADS = 512;
constexpr int   XPAD    = 272;   // x row stride (floats): makes 2-col STS conflict-free

struct SmemLayout {
    ulonglong2 a[12][THREADS];   // 96 KB: A pairs not held in registers
    float      x[2][2][XPAD];    // [buf][col][row], double-buffered state
};

__device__ __forceinline__ void fma2(unsigned long long& d,
                                     unsigned long long a,
                                     unsigned long long b) {
    asm("fma.rn.f32x2 %0, %1, %2, %0;" : "+l"(d) : "l"(a), "l"(b));
}
__device__ __forceinline__ unsigned long long pk2(float lo, float hi) {
    unsigned long long v;
    asm("mov.b64 %0, {%1, %2};" : "=l"(v) : "f"(lo), "f"(hi));
    return v;
}
__device__ __forceinline__ float2 upk2(unsigned long long v) {
    float2 r;
    asm("mov.b64 {%0, %1}, %2;" : "=f"(r.x), "=f"(r.y) : "l"(v));
    return r;
}

__device__ __forceinline__ float aval(const float* __restrict__ W, int i, int j) {
    if (j > i) return W[i * Nn + j];
    if (j < i) return -W[j * Nn + i];
    return -EPSF;
}

__global__ void __launch_bounds__(THREADS, 1)
antisym_rnn_kernel(const float* __restrict__ X0,
                   const float* __restrict__ W,
                   const float* __restrict__ by,
                   float* __restrict__ out) {
    extern __shared__ unsigned char smraw[];
    SmemLayout* sm = reinterpret_cast<SmemLayout*>(smraw);

    const int t    = threadIdx.x;
    const int w    = t >> 5;
    const int lane = t & 31;
    const int kc   = lane & 7;          // k-chunk: cols [32*kc, 32*kc+32)
    const int g    = lane >> 3;         // row-group within warp
    const int rg   = w * 4 + g;         // row-group 0..63 -> rows 4*rg .. 4*rg+3
    const int j0   = kc * 32;
    const int b0   = blockIdx.x * 2;

    // Reduction ownership: lane p = lane&7 ends holding value idx p = c*4 + r.
    const int p8      = lane & 7;
    const int row_out = 4 * rg + (p8 & 3);
    const int col_out = (p8 >> 2) & 1;
    const int lb0 = lane & 1, lb1 = (lane >> 1) & 1, lb2 = (lane >> 2) & 1;

    // ---- per-lane persistent state ----
    float x_own  = X0[(size_t)(b0 + col_out) * Nn + row_out];
    const float by_own = by[row_out];
    float* outp = out + ((size_t)(b0 + col_out) * Tmax) * Nn + row_out;

    // init x buffer 0 + t=0 output
    sm->x[0][col_out][row_out] = x_own;
    outp[0] = x_own;

    // ---- build A chunk: 4 rows (4rg..4rg+3) x 16 pairs (cols j0..j0+31) ----
    // pairs p=0..9 in regs (cols j0..j0+19), p=10..15 in smem (cols j0+20..j0+31)
    unsigned long long areg[40];
#pragma unroll
    for (int r = 0; r < 4; ++r) {
        const int row = 4 * rg + r;
#pragma unroll
        for (int p = 0; p < 10; ++p) {
            const int j = j0 + 2 * p;
            areg[r * 10 + p] = pk2(aval(W, row, j), aval(W, row, j + 1));
        }
#pragma unroll
        for (int pi = 5; pi < 8; ++pi) {
            const int j = j0 + 4 * pi;
            ulonglong2 v;
            v.x = pk2(aval(W, row, j),     aval(W, row, j + 1));
            v.y = pk2(aval(W, row, j + 2), aval(W, row, j + 3));
            sm->a[(pi - 5) * 4 + r][t] = v;
        }
    }
    __syncthreads();

    int pbuf = 0;
    for (int s = 1; s < Tmax; ++s) {
        const float* xa = &sm->x[pbuf][0][0] + j0;
        const float* xb = &sm->x[pbuf][1][0] + j0;

        // acc[idx], idx = c*4 + r
        unsigned long long acc[8];
#pragma unroll
        for (int i = 0; i < 8; ++i) acc[i] = 0ULL;

        // register-resident A (pairs 0..9 per row)
#pragma unroll
        for (int pi = 0; pi < 5; ++pi) {
            const ulonglong2 qa = *reinterpret_cast<const ulonglong2*>(xa + 4 * pi);
            const ulonglong2 qb = *reinterpret_cast<const ulonglong2*>(xb + 4 * pi);
#pragma unroll
            for (int r = 0; r < 4; ++r) {
                fma2(acc[r],     areg[r * 10 + 2 * pi],     qa.x);
                fma2(acc[r],     areg[r * 10 + 2 * pi + 1], qa.y);
                fma2(acc[4 + r], areg[r * 10 + 2 * pi],     qb.x);
                fma2(acc[4 + r], areg[r * 10 + 2 * pi + 1], qb.y);
            }
        }
        // smem-resident A (pairs 10..15 per row)
#pragma unroll
        for (int pi = 5; pi < 8; ++pi) {
            const ulonglong2 qa = *reinterpret_cast<const ulonglong2*>(xa + 4 * pi);
            const ulonglong2 qb = *reinterpret_cast<const ulonglong2*>(xb + 4 * pi);
#pragma unroll
            for (int r = 0; r < 4; ++r) {
                const ulonglong2 a2 = sm->a[(pi - 5) * 4 + r][t];
                fma2(acc[r],     a2.x, qa.x);
                fma2(acc[r],     a2.y, qa.y);
                fma2(acc[4 + r], a2.x, qb.x);
                fma2(acc[4 + r], a2.y, qb.y);
            }
        }

        // fold f32x2 pairs -> 8 scalars
        float v[8];
#pragma unroll
        for (int i = 0; i < 8; ++i) {
            const float2 f = upk2(acc[i]);
            v[i] = f.x + f.y;
        }

        // 3-round butterfly over the 8-lane kc-group: lane p ends with sum of v[p]
        float u[4];
#pragma unroll
        for (int k = 0; k < 4; ++k) {
            const float keep = lb0 ? v[2 * k + 1] : v[2 * k];
            const float send = lb0 ? v[2 * k]     : v[2 * k + 1];
            u[k] = keep + __shfl_xor_sync(0xFFFFFFFFu, send, 1);
        }
        float w2[2];
#pragma unroll
        for (int m = 0; m < 2; ++m) {
            const float keep = lb1 ? u[2 * m + 1] : u[2 * m];
            const float send = lb1 ? u[2 * m]     : u[2 * m + 1];
            w2[m] = keep + __shfl_xor_sync(0xFFFFFFFFu, send, 2);
        }
        {
            const float keep = lb2 ? w2[1] : w2[0];
            const float send = lb2 ? w2[0] : w2[1];
            const float y = keep + __shfl_xor_sync(0xFFFFFFFFu, send, 4) + by_own;
            x_own += STEPF * tanhf(y);
        }

        sm->x[1 - pbuf][col_out][row_out] = x_own;
        outp[(size_t)s * Nn] = x_own;
        __syncthreads();
        pbuf ^= 1;
    }
}

extern "C" void kernel_launch(void* const* d_in, const int* in_sizes, int n_in,
                              void* d_out, int out_size) {
    const float* X0 = (const float*)d_in[0];
    const float* W  = (const float*)d_in[1];
    const float* by = (const float*)d_in[2];
    float* out      = (float*)d_out;

    const int smem_bytes = (int)sizeof(SmemLayout);
    cudaFuncSetAttribute(antisym_rnn_kernel,
                         cudaFuncAttributeMaxDynamicSharedMemorySize, smem_bytes);

    antisym_rnn_kernel<<<128, THREADS, smem_bytes>>>(X0, W, by, out);
}

// round 7
// speedup vs baseline: 4.0321x; 4.0321x over previous
#include <cuda_runtime.h>
#include <cstdint>
#include <math.h>

// AntisymmetricRNN: x_{t+1} = x_t + 0.01*tanh(A x_t + by)
// A = triu(W,1) - triu(W,1)^T - eps*I.  N=256, BS=256, TMAX=1000.
// Persistent kernel: 128 CTAs x 2 batch columns; sequential over time.
// R7 = R5 structure (warp-local butterfly reduce, 1 barrier/step, state in regs)
//      + SKEWED x layout killing the 8-way bank conflict that sank R5:
//      chunk kc stored at float-offset kc*36 -> banks (4kc+4pi)%32 all distinct.

constexpr int   Nn      = 256;
constexpr int   Tmax    = 1000;
constexpr float STEPF   = 0.01f;
constexpr float EPSF    = 0.001f;
constexpr int   THREADS = 512;
constexpr int   CH      = 36;    // skewed chunk stride (floats): 32 data + 4 pad
constexpr int   COLSTR  = 304;   // col stride (floats): 8*36=288 +16 -> bank offset 16

struct SmemLayout {
    ulonglong2 a[12][THREADS];     // 96 KB: A pairs not held in registers
    float      x[2][2 * COLSTR];   // [buf][col*COLSTR + skewed row], double-buffered
};

__device__ __forceinline__ void fma2(unsigned long long& d,
                                     unsigned long long a,
                                     unsigned long long b) {
    asm("fma.rn.f32x2 %0, %1, %2, %0;" : "+l"(d) : "l"(a), "l"(b));
}
__device__ __forceinline__ unsigned long long pk2(float lo, float hi) {
    unsigned long long v;
    asm("mov.b64 %0, {%1, %2};" : "=l"(v) : "f"(lo), "f"(hi));
    return v;
}
__device__ __forceinline__ float2 upk2(unsigned long long v) {
    float2 r;
    asm("mov.b64 {%0, %1}, %2;" : "=f"(r.x), "=f"(r.y) : "l"(v));
    return r;
}

__device__ __forceinline__ float aval(const float* __restrict__ W, int i, int j) {
    if (j > i) return W[i * Nn + j];
    if (j < i) return -W[j * Nn + i];
    return -EPSF;
}

// skewed index for state element (col, row)
__device__ __forceinline__ int xidx(int col, int row) {
    return col * COLSTR + (row >> 5) * CH + (row & 31);
}

__global__ void __launch_bounds__(THREADS, 1)
antisym_rnn_kernel(const float* __restrict__ X0,
                   const float* __restrict__ W,
                   const float* __restrict__ by,
                   float* __restrict__ out) {
    extern __shared__ unsigned char smraw[];
    SmemLayout* sm = reinterpret_cast<SmemLayout*>(smraw);

    const int t    = threadIdx.x;
    const int w    = t >> 5;
    const int lane = t & 31;
    const int kc   = lane & 7;          // k-chunk: cols [32*kc, 32*kc+32)
    const int g    = lane >> 3;         // row-group within warp
    const int rg   = w * 4 + g;         // row-group 0..63 -> rows 4*rg .. 4*rg+3
    const int j0   = kc * 32;           // logical column base
    const int jsk  = kc * CH;           // skewed smem float offset of this chunk
    const int b0   = blockIdx.x * 2;

    // Reduction ownership: lane ends holding output idx p8 = col*4 + r.
    const int p8      = lane & 7;
    const int row_out = 4 * rg + (p8 & 3);
    const int col_out = (p8 >> 2) & 1;
    const int lb0 = lane & 1, lb1 = (lane >> 1) & 1, lb2 = (lane >> 2) & 1;
    const int own = xidx(col_out, row_out);

    // ---- per-lane persistent state ----
    float x_own        = X0[(size_t)(b0 + col_out) * Nn + row_out];
    const float by_own = by[row_out];
    float* outp = out + ((size_t)(b0 + col_out) * Tmax) * Nn + row_out;

    sm->x[0][own] = x_own;
    outp[0] = x_own;

    // ---- build A chunk: 4 rows (4rg..4rg+3) x 16 pairs (cols j0..j0+31) ----
    // pairs p=0..9 in regs (cols j0..j0+19), p=10..15 in smem (cols j0+20..j0+31)
    unsigned long long areg[40];
#pragma unroll
    for (int r = 0; r < 4; ++r) {
        const int row = 4 * rg + r;
#pragma unroll
        for (int p = 0; p < 10; ++p) {
            const int j = j0 + 2 * p;
            areg[r * 10 + p] = pk2(aval(W, row, j), aval(W, row, j + 1));
        }
#pragma unroll
        for (int pi = 5; pi < 8; ++pi) {
            const int j = j0 + 4 * pi;
            ulonglong2 v;
            v.x = pk2(aval(W, row, j),     aval(W, row, j + 1));
            v.y = pk2(aval(W, row, j + 2), aval(W, row, j + 3));
            sm->a[(pi - 5) * 4 + r][t] = v;
        }
    }
    __syncthreads();

    int pbuf = 0;
    for (int s = 1; s < Tmax; ++s) {
        const float* xa = &sm->x[pbuf][jsk];            // col 0, this chunk
        const float* xb = &sm->x[pbuf][COLSTR + jsk];   // col 1, this chunk

        // acc[idx], idx = c*4 + r
        unsigned long long acc[8];
#pragma unroll
        for (int i = 0; i < 8; ++i) acc[i] = 0ULL;

        // register-resident A (pairs 0..9 per row)
#pragma unroll
        for (int pi = 0; pi < 5; ++pi) {
            const ulonglong2 qa = *reinterpret_cast<const ulonglong2*>(xa + 4 * pi);
            const ulonglong2 qb = *reinterpret_cast<const ulonglong2*>(xb + 4 * pi);
#pragma unroll
            for (int r = 0; r < 4; ++r) {
                fma2(acc[r],     areg[r * 10 + 2 * pi],     qa.x);
                fma2(acc[r],     areg[r * 10 + 2 * pi + 1], qa.y);
                fma2(acc[4 + r], areg[r * 10 + 2 * pi],     qb.x);
                fma2(acc[4 + r], areg[r * 10 + 2 * pi + 1], qb.y);
            }
        }
        // smem-resident A (pairs 10..15 per row)
#pragma unroll
        for (int pi = 5; pi < 8; ++pi) {
            const ulonglong2 qa = *reinterpret_cast<const ulonglong2*>(xa + 4 * pi);
            const ulonglong2 qb = *reinterpret_cast<const ulonglong2*>(xb + 4 * pi);
#pragma unroll
            for (int r = 0; r < 4; ++r) {
                const ulonglong2 a2 = sm->a[(pi - 5) * 4 + r][t];
                fma2(acc[r],     a2.x, qa.x);
                fma2(acc[r],     a2.y, qa.y);
                fma2(acc[4 + r], a2.x, qb.x);
                fma2(acc[4 + r], a2.y, qb.y);
            }
        }

        // fold f32x2 pairs -> 8 scalars
        float v[8];
#pragma unroll
        for (int i = 0; i < 8; ++i) {
            const float2 f = upk2(acc[i]);
            v[i] = f.x + f.y;
        }

        // 3-round butterfly over the 8-lane kc-group: lane p8 ends with sum of v[p8]
        float u[4];
#pragma unroll
        for (int k = 0; k < 4; ++k) {
            const float keep = lb0 ? v[2 * k + 1] : v[2 * k];
            const float send = lb0 ? v[2 * k]     : v[2 * k + 1];
            u[k] = keep + __shfl_xor_sync(0xFFFFFFFFu, send, 1);
        }
        float w2[2];
#pragma unroll
        for (int m = 0; m < 2; ++m) {
            const float keep = lb1 ? u[2 * m + 1] : u[2 * m];
            const float send = lb1 ? u[2 * m]     : u[2 * m + 1];
            w2[m] = keep + __shfl_xor_sync(0xFFFFFFFFu, send, 2);
        }
        {
            const float keep = lb2 ? w2[1] : w2[0];
            const float send = lb2 ? w2[0] : w2[1];
            const float y = keep + __shfl_xor_sync(0xFFFFFFFFu, send, 4) + by_own;
            x_own += STEPF * tanhf(y);
        }

        sm->x[1 - pbuf][own] = x_own;
        outp[(size_t)s * Nn] = x_own;
        __syncthreads();
        pbuf ^= 1;
    }
}

extern "C" void kernel_launch(void* const* d_in, const int* in_sizes, int n_in,
                              void* d_out, int out_size) {
    const float* X0 = (const float*)d_in[0];
    const float* W  = (const float*)d_in[1];
    const float* by = (const float*)d_in[2];
    float* out      = (float*)d_out;

    const int smem_bytes = (int)sizeof(SmemLayout);
    cudaFuncSetAttribute(antisym_rnn_kernel,
                         cudaFuncAttributeMaxDynamicSharedMemorySize, smem_bytes);

    antisym_rnn_kernel<<<128, THREADS, smem_bytes>>>(X0, W, by, out);
}